// round 1
// baseline (speedup 1.0000x reference)
#include <cuda_runtime.h>

#define EMB   1024
#define NH    16
#define HD    64
#define BATCH 2
#define SEQ   2048
#define MTOK  (BATCH*SEQ)   // 4096
#define BHN   (BATCH*NH)    // 32
#define KDIM  EMB

// Scratch (allocation-free rule: __device__ globals)
__device__ float g_Q[(size_t)BHN*SEQ*HD];      // [BH][S][D], pre-scaled by 0.125*log2(e)
__device__ float g_K[(size_t)BHN*SEQ*HD];
__device__ float g_V[(size_t)BHN*SEQ*HD];
__device__ float g_attn[(size_t)MTOK*EMB];     // [B*S][E]

// ---------------------------------------------------------------------------
// 128x128x8 SGEMM tile: C[m,n] = sum_k A[m,k] * W[n,k]   (both K-contiguous)
// 256 threads, 8x8 accum per thread.
// ---------------------------------------------------------------------------
__device__ __forceinline__ void gemm_tile_128(
    const float* __restrict__ A, const float* __restrict__ W,
    int m0, int n0, float (&acc)[8][8])
{
    __shared__ float As[8][128];
    __shared__ float Bs[8][128];

    const int tid  = threadIdx.x;
    const int lrow = tid >> 1;          // 0..127
    const int lseg = (tid & 1) << 2;    // 0 or 4
    const float* Ap = A + (size_t)(m0 + lrow) * KDIM + lseg;
    const float* Wp = W + (size_t)(n0 + lrow) * KDIM + lseg;
    const int ty = tid >> 4, tx = tid & 15;

    for (int k0 = 0; k0 < KDIM; k0 += 8) {
        float4 av = *(const float4*)(Ap + k0);
        float4 wv = *(const float4*)(Wp + k0);
        __syncthreads();
        As[lseg+0][lrow] = av.x; As[lseg+1][lrow] = av.y;
        As[lseg+2][lrow] = av.z; As[lseg+3][lrow] = av.w;
        Bs[lseg+0][lrow] = wv.x; Bs[lseg+1][lrow] = wv.y;
        Bs[lseg+2][lrow] = wv.z; Bs[lseg+3][lrow] = wv.w;
        __syncthreads();
        #pragma unroll
        for (int kk = 0; kk < 8; kk++) {
            float a[8], b[8];
            *(float4*)(a)   = *(const float4*)&As[kk][ty*8];
            *(float4*)(a+4) = *(const float4*)&As[kk][ty*8+4];
            *(float4*)(b)   = *(const float4*)&Bs[kk][tx*8];
            *(float4*)(b+4) = *(const float4*)&Bs[kk][tx*8+4];
            #pragma unroll
            for (int i = 0; i < 8; i++)
                #pragma unroll
                for (int j = 0; j < 8; j++)
                    acc[i][j] = fmaf(a[i], b[j], acc[i][j]);
        }
    }
}

// ---------------------------------------------------------------------------
// QKV projection. blockIdx.z selects which of Q/K/V. Epilogue adds bias,
// applies alpha (Q gets 0.125*log2e folded in), scatters to [BH][S][D].
// ---------------------------------------------------------------------------
__global__ __launch_bounds__(256) void proj_qkv_kernel(
    const float* __restrict__ X,
    const float* __restrict__ Wq, const float* __restrict__ bq,
    const float* __restrict__ Wk, const float* __restrict__ bk,
    const float* __restrict__ Wv, const float* __restrict__ bv)
{
    const float* W; const float* bias; float* dst; float alpha;
    if (blockIdx.z == 0)      { W = Wq; bias = bq; dst = g_Q; alpha = 0.125f * 1.4426950408889634f; }
    else if (blockIdx.z == 1) { W = Wk; bias = bk; dst = g_K; alpha = 1.0f; }
    else                      { W = Wv; bias = bv; dst = g_V; alpha = 1.0f; }

    const int m0 = blockIdx.y << 7;
    const int n0 = blockIdx.x << 7;
    float acc[8][8] = {};
    gemm_tile_128(X, W, m0, n0, acc);

    const int tid = threadIdx.x;
    const int ty = tid >> 4, tx = tid & 15;
    #pragma unroll
    for (int i = 0; i < 8; i++) {
        int m = m0 + ty*8 + i;
        int b = m >> 11;               // m / SEQ
        int s = m & (SEQ-1);
        #pragma unroll
        for (int j4 = 0; j4 < 2; j4++) {
            int n = n0 + tx*8 + j4*4;
            int h = n >> 6;
            int d = n & 63;            // multiple of 4 -> float4 ok
            float4 v;
            v.x = (acc[i][j4*4+0] + bias[n+0]) * alpha;
            v.y = (acc[i][j4*4+1] + bias[n+1]) * alpha;
            v.z = (acc[i][j4*4+2] + bias[n+2]) * alpha;
            v.w = (acc[i][j4*4+3] + bias[n+3]) * alpha;
            *(float4*)&dst[((size_t)(b*NH + h)*SEQ + s)*HD + d] = v;
        }
    }
}

// ---------------------------------------------------------------------------
// Flash attention fp32. Grid (S/64, B*H). 256 threads (16x16), each owns a
// 4x4 of the 64x64 score tile and a 4x4 of the 64x64 output tile.
// Smem: Q, K (reused as P after scores), V -> exactly 48KB.
// XOR swizzle on float4 columns: c4 ^= (r>>2)&15 — conflict-free for all
// access patterns used below.
// ---------------------------------------------------------------------------
#define SW(r,c4) ((r)*64 + ((((c4) ^ (((r)>>2)&15))) << 2))

__global__ __launch_bounds__(256) void attn_kernel()
{
    __shared__ float Qs[64*64];
    __shared__ float Ks[64*64];   // becomes P after scores are consumed
    __shared__ float Vs[64*64];

    const int tid = threadIdx.x;
    const int ty = tid >> 4, tx = tid & 15;
    const int bh = blockIdx.y;
    const int q0 = blockIdx.x << 6;

    const float* Qg = g_Q + ((size_t)bh*SEQ + q0)*HD;
    const float* Kg = g_K + (size_t)bh*SEQ*HD;
    const float* Vg = g_V + (size_t)bh*SEQ*HD;

    for (int idx = tid; idx < 64*16; idx += 256) {
        int r = idx >> 4, c4 = idx & 15;
        *(float4*)&Qs[SW(r,c4)] = *(const float4*)(Qg + (size_t)r*HD + c4*4);
    }

    float o[4][4] = {};
    float mi[4], li[4];
    #pragma unroll
    for (int i = 0; i < 4; i++) { mi[i] = __int_as_float(0xff800000); li[i] = 0.f; }

    for (int kb = 0; kb < SEQ; kb += 64) {
        __syncthreads();                       // prior-iter P/V reads done
        for (int idx = tid; idx < 64*16; idx += 256) {
            int r = idx >> 4, c4 = idx & 15;
            *(float4*)&Ks[SW(r,c4)] = *(const float4*)(Kg + (size_t)(kb+r)*HD + c4*4);
            *(float4*)&Vs[SW(r,c4)] = *(const float4*)(Vg + (size_t)(kb+r)*HD + c4*4);
        }
        __syncthreads();

        // S = Q K^T  (Q already carries 0.125*log2e)
        float s[4][4] = {};
        #pragma unroll
        for (int d4 = 0; d4 < 16; d4++) {
            float4 qv[4], kv[4];
            #pragma unroll
            for (int i = 0; i < 4; i++) qv[i] = *(const float4*)&Qs[SW(4*ty+i, d4)];
            #pragma unroll
            for (int j = 0; j < 4; j++) kv[j] = *(const float4*)&Ks[SW(4*tx+j, d4)];
            #pragma unroll
            for (int i = 0; i < 4; i++)
                #pragma unroll
                for (int j = 0; j < 4; j++) {
                    s[i][j] = fmaf(qv[i].x, kv[j].x, s[i][j]);
                    s[i][j] = fmaf(qv[i].y, kv[j].y, s[i][j]);
                    s[i][j] = fmaf(qv[i].z, kv[j].z, s[i][j]);
                    s[i][j] = fmaf(qv[i].w, kv[j].w, s[i][j]);
                }
        }

        __syncthreads();                       // everyone done reading Ks before P overwrites it

        // online softmax (row reductions across tx via shfl-xor; offs 1..8 stay in-warp on tx bits)
        #pragma unroll
        for (int i = 0; i < 4; i++) {
            float rm = fmaxf(fmaxf(s[i][0], s[i][1]), fmaxf(s[i][2], s[i][3]));
            #pragma unroll
            for (int off = 8; off >= 1; off >>= 1)
                rm = fmaxf(rm, __shfl_xor_sync(0xffffffffu, rm, off));
            float mnew = fmaxf(mi[i], rm);
            float corr = exp2f(mi[i] - mnew);
            mi[i] = mnew;
            float4 p;
            p.x = exp2f(s[i][0] - mnew);
            p.y = exp2f(s[i][1] - mnew);
            p.z = exp2f(s[i][2] - mnew);
            p.w = exp2f(s[i][3] - mnew);
            float rs = (p.x + p.y) + (p.z + p.w);
            #pragma unroll
            for (int off = 8; off >= 1; off >>= 1)
                rs += __shfl_xor_sync(0xffffffffu, rs, off);
            li[i] = li[i] * corr + rs;
            #pragma unroll
            for (int j = 0; j < 4; j++) o[i][j] *= corr;
            *(float4*)&Ks[SW(4*ty+i, tx)] = p;     // P tile into Ks
        }
        __syncthreads();

        // O += P @ V
        #pragma unroll
        for (int c4 = 0; c4 < 16; c4++) {
            float4 pv[4];
            #pragma unroll
            for (int i = 0; i < 4; i++) pv[i] = *(const float4*)&Ks[SW(4*ty+i, c4)];
            #pragma unroll
            for (int cc = 0; cc < 4; cc++) {
                float4 vv = *(const float4*)&Vs[SW(4*c4+cc, tx)];
                #pragma unroll
                for (int i = 0; i < 4; i++) {
                    float p = (cc==0) ? pv[i].x : (cc==1) ? pv[i].y : (cc==2) ? pv[i].z : pv[i].w;
                    o[i][0] = fmaf(p, vv.x, o[i][0]);
                    o[i][1] = fmaf(p, vv.y, o[i][1]);
                    o[i][2] = fmaf(p, vv.z, o[i][2]);
                    o[i][3] = fmaf(p, vv.w, o[i][3]);
                }
            }
        }
    }

    // epilogue: normalize, write [B,S,E] with e = h*64+d
    const int b = bh >> 4, h = bh & 15;
    #pragma unroll
    for (int i = 0; i < 4; i++) {
        float inv = 1.0f / li[i];
        int srow = q0 + 4*ty + i;
        float4 v = make_float4(o[i][0]*inv, o[i][1]*inv, o[i][2]*inv, o[i][3]*inv);
        *(float4*)&g_attn[((size_t)(b*SEQ + srow))*EMB + h*HD + 4*tx] = v;
    }
}

// ---------------------------------------------------------------------------
// Output projection: d_out = g_attn @ Wo^T + bo
// ---------------------------------------------------------------------------
__global__ __launch_bounds__(256) void out_proj_kernel(
    const float* __restrict__ Wo, const float* __restrict__ bo,
    float* __restrict__ out)
{
    const int m0 = blockIdx.y << 7;
    const int n0 = blockIdx.x << 7;
    float acc[8][8] = {};
    gemm_tile_128(g_attn, Wo, m0, n0, acc);

    const int tid = threadIdx.x;
    const int ty = tid >> 4, tx = tid & 15;
    #pragma unroll
    for (int i = 0; i < 8; i++) {
        int m = m0 + ty*8 + i;
        #pragma unroll
        for (int j4 = 0; j4 < 2; j4++) {
            int n = n0 + tx*8 + j4*4;
            float4 v;
            v.x = acc[i][j4*4+0] + bo[n+0];
            v.y = acc[i][j4*4+1] + bo[n+1];
            v.z = acc[i][j4*4+2] + bo[n+2];
            v.w = acc[i][j4*4+3] + bo[n+3];
            *(float4*)&out[(size_t)m*EMB + n] = v;
        }
    }
}

extern "C" void kernel_launch(void* const* d_in, const int* in_sizes, int n_in,
                              void* d_out, int out_size)
{
    (void)in_sizes; (void)n_in; (void)out_size;
    const float* x  = (const float*)d_in[0];
    const float* Wq = (const float*)d_in[1];
    const float* bq = (const float*)d_in[2];
    const float* Wk = (const float*)d_in[3];
    const float* bk = (const float*)d_in[4];
    const float* Wv = (const float*)d_in[5];
    const float* bv = (const float*)d_in[6];
    const float* Wo = (const float*)d_in[7];
    const float* bo = (const float*)d_in[8];
    float* out = (float*)d_out;

    dim3 gproj(EMB/128, MTOK/128, 3);        // 8 x 32 x 3
    proj_qkv_kernel<<<gproj, 256>>>(x, Wq, bq, Wk, bk, Wv, bv);

    dim3 gattn(SEQ/64, BHN);                 // 32 x 32
    attn_kernel<<<gattn, 256>>>();

    dim3 gout(EMB/128, MTOK/128);            // 8 x 32
    out_proj_kernel<<<gout, 256>>>(Wo, bo, out);
}

// round 3
// speedup vs baseline: 2.9674x; 2.9674x over previous
#include <cuda_runtime.h>
#include <cuda_bf16.h>
#include <cstdint>

#define EMB   1024
#define NH    16
#define HD    64
#define BATCH 2
#define SEQ   2048
#define MTOK  (BATCH*SEQ)   // 4096
#define BHN   (BATCH*NH)    // 32

// ---------------- scratch (__device__ globals; no allocs allowed) -----------
__device__ __nv_bfloat16 g_Xhi[(size_t)MTOK*EMB], g_Xlo[(size_t)MTOK*EMB];
__device__ __nv_bfloat16 g_Ahi[(size_t)MTOK*EMB], g_Alo[(size_t)MTOK*EMB];
__device__ __nv_bfloat16 g_Qh[(size_t)MTOK*EMB], g_Ql[(size_t)MTOK*EMB];
__device__ __nv_bfloat16 g_Kh[(size_t)MTOK*EMB], g_Kl[(size_t)MTOK*EMB];
__device__ __nv_bfloat16 g_Vh[(size_t)MTOK*EMB], g_Vl[(size_t)MTOK*EMB];
__device__ __nv_bfloat16 g_Wqh[(size_t)EMB*EMB], g_Wql[(size_t)EMB*EMB];
__device__ __nv_bfloat16 g_Wkh[(size_t)EMB*EMB], g_Wkl[(size_t)EMB*EMB];
__device__ __nv_bfloat16 g_Wvh[(size_t)EMB*EMB], g_Wvl[(size_t)EMB*EMB];
__device__ __nv_bfloat16 g_Woh[(size_t)EMB*EMB], g_Wol[(size_t)EMB*EMB];

// ---------------- helpers ---------------------------------------------------
__device__ __forceinline__ uint32_t smem_u32(const void* p) {
    uint32_t a;
    asm("{ .reg .u64 t; cvta.to.shared.u64 t, %1; cvt.u32.u64 %0, t; }" : "=r"(a) : "l"(p));
    return a;
}
__device__ __forceinline__ void cp16(uint32_t d, const void* s) {
    asm volatile("cp.async.cg.shared.global [%0], [%1], 16;" :: "r"(d), "l"(s));
}
#define CP_COMMIT() asm volatile("cp.async.commit_group;")
#define CP_WAIT(n)  asm volatile("cp.async.wait_group %0;" :: "n"(n))

__device__ __forceinline__ void ldsm4(uint32_t (&r)[4], uint32_t a) {
    asm volatile("ldmatrix.sync.aligned.m8n8.x4.shared.b16 {%0,%1,%2,%3}, [%4];"
        : "=r"(r[0]), "=r"(r[1]), "=r"(r[2]), "=r"(r[3]) : "r"(a));
}
__device__ __forceinline__ void ldsm4t(uint32_t (&r)[4], uint32_t a) {
    asm volatile("ldmatrix.sync.aligned.m8n8.x4.trans.shared.b16 {%0,%1,%2,%3}, [%4];"
        : "=r"(r[0]), "=r"(r[1]), "=r"(r[2]), "=r"(r[3]) : "r"(a));
}
__device__ __forceinline__ void mma_bf(float (&c)[4], const uint32_t (&a)[4], uint32_t b0, uint32_t b1) {
    asm volatile("mma.sync.aligned.m16n8k16.row.col.f32.bf16.bf16.f32 "
        "{%0,%1,%2,%3}, {%4,%5,%6,%7}, {%8,%9}, {%0,%1,%2,%3};"
        : "+f"(c[0]), "+f"(c[1]), "+f"(c[2]), "+f"(c[3])
        : "r"(a[0]), "r"(a[1]), "r"(a[2]), "r"(a[3]), "r"(b0), "r"(b1));
}
__device__ __forceinline__ uint32_t packbf(float lo, float hi) {
    uint32_t r; asm("cvt.rn.bf16x2.f32 %0, %1, %2;" : "=r"(r) : "f"(hi), "f"(lo)); return r;
}
__device__ __forceinline__ void split2(float v0, float v1, uint32_t &hp, uint32_t &lp) {
    hp = packbf(v0, v1);
    float h0 = __uint_as_float(hp << 16);
    float h1 = __uint_as_float(hp & 0xFFFF0000u);
    lp = packbf(v0 - h0, v1 - h1);
}

// ---------------- fp32 -> bf16 hi/lo split ----------------------------------
__global__ __launch_bounds__(256) void split_kernel(const float* __restrict__ x,
                                                    __nv_bfloat16* __restrict__ hi,
                                                    __nv_bfloat16* __restrict__ lo, int n8)
{
    int i = blockIdx.x * 256 + threadIdx.x;
    if (i >= n8) return;
    float4 a = ((const float4*)x)[2*i];
    float4 b = ((const float4*)x)[2*i + 1];
    float v[8] = {a.x, a.y, a.z, a.w, b.x, b.y, b.z, b.w};
    uint32_t hp[4], lp[4];
    #pragma unroll
    for (int j = 0; j < 4; j++) split2(v[2*j], v[2*j+1], hp[j], lp[j]);
    ((uint4*)hi)[i] = make_uint4(hp[0], hp[1], hp[2], hp[3]);
    ((uint4*)lo)[i] = make_uint4(lp[0], lp[1], lp[2], lp[3]);
}

// ---------------- mma.sync GEMM body: 128x128 tile, C = A @ W^T (split) -----
#define SPAD  80
#define ALOFF 10240
#define BOFF  20480
#define BLOFF 30720
#define PSTG  40960
#define GEMM_SMEM (2*PSTG)   // 81920
#define NITER (EMB/32)       // 32

__device__ __forceinline__ void gemm_body_128(
    const __nv_bfloat16* __restrict__ Ah, const __nv_bfloat16* __restrict__ Al,
    const __nv_bfloat16* __restrict__ Wh, const __nv_bfloat16* __restrict__ Wl,
    int m0, int n0, float (&acc)[2][8][4])
{
    extern __shared__ char sm[];
    const uint32_t smb = smem_u32(sm);
    const int tid = threadIdx.x, lane = tid & 31, wid = tid >> 5;
    const int wm = wid & 3, wn = wid >> 2;

    auto issue = [&](int it) {
        const int k0 = it << 5;
        const uint32_t sb = smb + (it & 1) * PSTG;
        #pragma unroll
        for (int j = 0; j < 2; ++j) {
            int idx = tid + (j << 8);
            int row = idx >> 2, seg = idx & 3;
            uint32_t so = row * SPAD + seg * 16;
            size_t ga = (size_t)(m0 + row) * EMB + k0 + seg * 8;
            size_t gb = (size_t)(n0 + row) * EMB + k0 + seg * 8;
            cp16(sb + so,         Ah + ga);
            cp16(sb + ALOFF + so, Al + ga);
            cp16(sb + BOFF  + so, Wh + gb);
            cp16(sb + BLOFF + so, Wl + gb);
        }
        CP_COMMIT();
    };

    issue(0);
    for (int it = 0; it < NITER; ++it) {
        if (it + 1 < NITER) { issue(it + 1); CP_WAIT(1); }
        else CP_WAIT(0);
        __syncthreads();
        const uint32_t sb = smb + (it & 1) * PSTG;
        #pragma unroll
        for (int ks = 0; ks < 2; ++ks) {
            uint32_t aH[2][4], aL[2][4];
            #pragma unroll
            for (int mf = 0; mf < 2; ++mf) {
                uint32_t row = wm*32 + mf*16 + ((lane>>3)&1)*8 + (lane&7);
                uint32_t col = ks*32 + ((lane>>4)&1)*16;
                ldsm4(aH[mf], sb + row*SPAD + col);
                ldsm4(aL[mf], sb + ALOFF + row*SPAD + col);
            }
            #pragma unroll
            for (int ng = 0; ng < 4; ++ng) {
                uint32_t bH[4], bL[4];
                uint32_t row = wn*64 + ng*16 + ((lane>>4)&1)*8 + (lane&7);
                uint32_t col = ks*32 + ((lane>>3)&1)*16;
                ldsm4(bH, sb + BOFF  + row*SPAD + col);
                ldsm4(bL, sb + BLOFF + row*SPAD + col);
                #pragma unroll
                for (int mf = 0; mf < 2; ++mf) {
                    mma_bf(acc[mf][2*ng],   aH[mf], bH[0], bH[1]);
                    mma_bf(acc[mf][2*ng],   aH[mf], bL[0], bL[1]);
                    mma_bf(acc[mf][2*ng],   aL[mf], bH[0], bH[1]);
                    mma_bf(acc[mf][2*ng+1], aH[mf], bH[2], bH[3]);
                    mma_bf(acc[mf][2*ng+1], aH[mf], bL[2], bL[3]);
                    mma_bf(acc[mf][2*ng+1], aL[mf], bH[2], bH[3]);
                }
            }
        }
        __syncthreads();
    }
}

// ---------------- QKV projection: epilogue -> bf16 hi/lo head-major ---------
__global__ void __launch_bounds__(256, 2) qkv_kernel(
    const float* __restrict__ bq, const float* __restrict__ bk, const float* __restrict__ bv)
{
    const __nv_bfloat16 *Wh, *Wl; const float* bias;
    __nv_bfloat16 *dh, *dl; float alpha;
    if (blockIdx.z == 0)      { Wh = g_Wqh; Wl = g_Wql; bias = bq; dh = g_Qh; dl = g_Ql; alpha = 0.18033688011112042f; }
    else if (blockIdx.z == 1) { Wh = g_Wkh; Wl = g_Wkl; bias = bk; dh = g_Kh; dl = g_Kl; alpha = 1.0f; }
    else                      { Wh = g_Wvh; Wl = g_Wvl; bias = bv; dh = g_Vh; dl = g_Vl; alpha = 1.0f; }

    const int m0 = blockIdx.y << 7, n0 = blockIdx.x << 7;
    float acc[2][8][4] = {};
    gemm_body_128(g_Xhi, g_Xlo, Wh, Wl, m0, n0, acc);

    const int lane = threadIdx.x & 31, wid = threadIdx.x >> 5;
    const int wm = wid & 3, wn = wid >> 2;
    #pragma unroll
    for (int mf = 0; mf < 2; ++mf)
        #pragma unroll
        for (int hh = 0; hh < 2; ++hh) {
            int m = m0 + wm*32 + mf*16 + hh*8 + (lane >> 2);
            int b = m >> 11, s = m & (SEQ-1);
            #pragma unroll
            for (int nf = 0; nf < 8; ++nf) {
                int n = n0 + wn*64 + nf*8 + (lane & 3)*2;
                int h = n >> 6, d = n & 63;
                float v0 = (acc[mf][nf][hh*2+0] + bias[n])   * alpha;
                float v1 = (acc[mf][nf][hh*2+1] + bias[n+1]) * alpha;
                uint32_t hp, lp; split2(v0, v1, hp, lp);
                size_t o = ((size_t)(b*NH + h)*SEQ + s)*HD + d;
                *(uint32_t*)(dh + o) = hp;
                *(uint32_t*)(dl + o) = lp;
            }
        }
}

// ---------------- output projection: epilogue -> fp32 d_out -----------------
__global__ void __launch_bounds__(256, 2) outproj_kernel(
    const float* __restrict__ bo, float* __restrict__ out)
{
    const int m0 = blockIdx.y << 7, n0 = blockIdx.x << 7;
    float acc[2][8][4] = {};
    gemm_body_128(g_Ahi, g_Alo, g_Woh, g_Wol, m0, n0, acc);

    const int lane = threadIdx.x & 31, wid = threadIdx.x >> 5;
    const int wm = wid & 3, wn = wid >> 2;
    #pragma unroll
    for (int mf = 0; mf < 2; ++mf)
        #pragma unroll
        for (int hh = 0; hh < 2; ++hh) {
            int m = m0 + wm*32 + mf*16 + hh*8 + (lane >> 2);
            #pragma unroll
            for (int nf = 0; nf < 8; ++nf) {
                int n = n0 + wn*64 + nf*8 + (lane & 3)*2;
                float2 v = make_float2(acc[mf][nf][hh*2+0] + bo[n],
                                       acc[mf][nf][hh*2+1] + bo[n+1]);
                *(float2*)&out[(size_t)m * EMB + n] = v;
            }
        }
}

// ---------------- mma.sync flash attention (split bf16) ---------------------
#define ASP     144
#define QL_OFF  18432
#define KV_BASE 36864
#define KL_OFF  9216
#define VH_OFF  18432
#define VL_OFF  27648
#define KV_STG  36864
#define ATT_SMEM (KV_BASE + 2*KV_STG)   // 110592

__global__ void __launch_bounds__(256, 2) attn_kernel()
{
    extern __shared__ char sm[];
    const uint32_t smb = smem_u32(sm);
    const int tid = threadIdx.x, lane = tid & 31, w = tid >> 5;
    const int bh = blockIdx.y, q0 = blockIdx.x << 7;

    const __nv_bfloat16* Qh = g_Qh + ((size_t)bh*SEQ + q0)*HD;
    const __nv_bfloat16* Ql = g_Ql + ((size_t)bh*SEQ + q0)*HD;
    const __nv_bfloat16* Kh = g_Kh + (size_t)bh*SEQ*HD;
    const __nv_bfloat16* Kl = g_Kl + (size_t)bh*SEQ*HD;
    const __nv_bfloat16* Vh = g_Vh + (size_t)bh*SEQ*HD;
    const __nv_bfloat16* Vl = g_Vl + (size_t)bh*SEQ*HD;

    auto issue_kv = [&](int it) {
        const int kv0 = it << 6;
        const uint32_t sb = smb + KV_BASE + (it & 1) * KV_STG;
        #pragma unroll
        for (int j = 0; j < 2; ++j) {
            int idx = tid + (j << 8);
            int row = idx >> 3, seg = idx & 7;
            size_t ga = (size_t)(kv0 + row)*HD + seg*8;
            uint32_t so = row*ASP + seg*16;
            cp16(sb + so,          Kh + ga);
            cp16(sb + KL_OFF + so, Kl + ga);
            cp16(sb + VH_OFF + so, Vh + ga);
            cp16(sb + VL_OFF + so, Vl + ga);
        }
        CP_COMMIT();
    };

    // load Q (128x64 hi/lo) + first KV stage, one group each
    #pragma unroll
    for (int j = 0; j < 4; ++j) {
        int idx = tid + (j << 8);
        int row = idx >> 3, seg = idx & 7;
        uint32_t so = row*ASP + seg*16;
        cp16(smb + so,          Qh + (size_t)row*HD + seg*8);
        cp16(smb + QL_OFF + so, Ql + (size_t)row*HD + seg*8);
    }
    issue_kv(0);

    float o[8][4] = {};
    float m0_ = __int_as_float(0xff800000), m1_ = m0_;
    float l0_ = 0.f, l1_ = 0.f;

    for (int it = 0; it < SEQ/64; ++it) {
        if (it + 1 < SEQ/64) { issue_kv(it + 1); CP_WAIT(1); }
        else CP_WAIT(0);
        __syncthreads();
        const uint32_t kb = smb + KV_BASE + (it & 1) * KV_STG;

        // S = Q K^T (contraction over d)
        float s[8][4] = {};
        #pragma unroll
        for (int ks = 0; ks < 4; ++ks) {
            uint32_t aQh[4], aQl[4];
            uint32_t qrow = w*16 + ((lane>>3)&1)*8 + (lane&7);
            uint32_t qcol = ks*32 + ((lane>>4)&1)*16;
            ldsm4(aQh, smb + qrow*ASP + qcol);
            ldsm4(aQl, smb + QL_OFF + qrow*ASP + qcol);
            #pragma unroll
            for (int ng = 0; ng < 4; ++ng) {
                uint32_t bH[4], bL[4];
                uint32_t krow = ng*16 + ((lane>>4)&1)*8 + (lane&7);
                uint32_t kcol = ks*32 + ((lane>>3)&1)*16;
                ldsm4(bH, kb + krow*ASP + kcol);
                ldsm4(bL, kb + KL_OFF + krow*ASP + kcol);
                mma_bf(s[2*ng],   aQh, bH[0], bH[1]);
                mma_bf(s[2*ng],   aQh, bL[0], bL[1]);
                mma_bf(s[2*ng],   aQl, bH[0], bH[1]);
                mma_bf(s[2*ng+1], aQh, bH[2], bH[3]);
                mma_bf(s[2*ng+1], aQh, bL[2], bL[3]);
                mma_bf(s[2*ng+1], aQl, bH[2], bH[3]);
            }
        }

        // online softmax (rows: lane/4 and lane/4+8; cols spread over lane%4 quads)
        float mx0 = fmaxf(s[0][0], s[0][1]), mx1 = fmaxf(s[0][2], s[0][3]);
        #pragma unroll
        for (int j = 1; j < 8; ++j) {
            mx0 = fmaxf(mx0, fmaxf(s[j][0], s[j][1]));
            mx1 = fmaxf(mx1, fmaxf(s[j][2], s[j][3]));
        }
        mx0 = fmaxf(mx0, __shfl_xor_sync(0xffffffffu, mx0, 1));
        mx0 = fmaxf(mx0, __shfl_xor_sync(0xffffffffu, mx0, 2));
        mx1 = fmaxf(mx1, __shfl_xor_sync(0xffffffffu, mx1, 1));
        mx1 = fmaxf(mx1, __shfl_xor_sync(0xffffffffu, mx1, 2));
        float mn0 = fmaxf(m0_, mx0), mn1 = fmaxf(m1_, mx1);
        float c0 = exp2f(m0_ - mn0), c1 = exp2f(m1_ - mn1);
        m0_ = mn0; m1_ = mn1;
        float a0 = 0.f, a1 = 0.f;
        #pragma unroll
        for (int j = 0; j < 8; ++j) {
            s[j][0] = exp2f(s[j][0] - mn0); s[j][1] = exp2f(s[j][1] - mn0);
            s[j][2] = exp2f(s[j][2] - mn1); s[j][3] = exp2f(s[j][3] - mn1);
            a0 += s[j][0] + s[j][1];
            a1 += s[j][2] + s[j][3];
        }
        a0 += __shfl_xor_sync(0xffffffffu, a0, 1);
        a0 += __shfl_xor_sync(0xffffffffu, a0, 2);
        a1 += __shfl_xor_sync(0xffffffffu, a1, 1);
        a1 += __shfl_xor_sync(0xffffffffu, a1, 2);
        l0_ = l0_ * c0 + a0;
        l1_ = l1_ * c1 + a1;
        #pragma unroll
        for (int j = 0; j < 8; ++j) {
            o[j][0] *= c0; o[j][1] *= c0; o[j][2] *= c1; o[j][3] *= c1;
        }

        // O += P V (contraction over kv); P packed in-register (accum == A-frag layout)
        #pragma unroll
        for (int ks = 0; ks < 4; ++ks) {
            uint32_t aPh[4], aPl[4];
            split2(s[2*ks][0],   s[2*ks][1],   aPh[0], aPl[0]);
            split2(s[2*ks][2],   s[2*ks][3],   aPh[1], aPl[1]);
            split2(s[2*ks+1][0], s[2*ks+1][1], aPh[2], aPl[2]);
            split2(s[2*ks+1][2], s[2*ks+1][3], aPh[3], aPl[3]);
            #pragma unroll
            for (int ng = 0; ng < 4; ++ng) {
                uint32_t bH[4], bL[4];
                uint32_t vrow = ks*16 + ((lane>>3)&1)*8 + (lane&7);
                uint32_t vcol = ng*32 + ((lane>>4)&1)*16;
                ldsm4t(bH, kb + VH_OFF + vrow*ASP + vcol);
                ldsm4t(bL, kb + VL_OFF + vrow*ASP + vcol);
                mma_bf(o[2*ng],   aPh, bH[0], bH[1]);
                mma_bf(o[2*ng],   aPh, bL[0], bL[1]);
                mma_bf(o[2*ng],   aPl, bH[0], bH[1]);
                mma_bf(o[2*ng+1], aPh, bH[2], bH[3]);
                mma_bf(o[2*ng+1], aPh, bL[2], bL[3]);
                mma_bf(o[2*ng+1], aPl, bH[2], bH[3]);
            }
        }
        __syncthreads();
    }

    // epilogue -> bf16 hi/lo in [B*S][EMB] for the output projection
    float inv0 = 1.0f / l0_, inv1 = 1.0f / l1_;
    const int b = bh >> 4, h = bh & 15;
    const int r0 = q0 + w*16 + (lane >> 2), r1 = r0 + 8;
    #pragma unroll
    for (int nf = 0; nf < 8; ++nf) {
        int d = nf*8 + (lane & 3)*2;
        int e = h*HD + d;
        uint32_t hp, lp;
        split2(o[nf][0]*inv0, o[nf][1]*inv0, hp, lp);
        size_t o0 = ((size_t)(b*SEQ + r0))*EMB + e;
        *(uint32_t*)(g_Ahi + o0) = hp;
        *(uint32_t*)(g_Alo + o0) = lp;
        split2(o[nf][2]*inv1, o[nf][3]*inv1, hp, lp);
        size_t o1 = ((size_t)(b*SEQ + r1))*EMB + e;
        *(uint32_t*)(g_Ahi + o1) = hp;
        *(uint32_t*)(g_Alo + o1) = lp;
    }
}

// ---------------------------------------------------------------------------
extern "C" void kernel_launch(void* const* d_in, const int* in_sizes, int n_in,
                              void* d_out, int out_size)
{
    (void)in_sizes; (void)n_in; (void)out_size;
    const float* x  = (const float*)d_in[0];
    const float* Wq = (const float*)d_in[1];
    const float* bq = (const float*)d_in[2];
    const float* Wk = (const float*)d_in[3];
    const float* bk = (const float*)d_in[4];
    const float* Wv = (const float*)d_in[5];
    const float* bv = (const float*)d_in[6];
    const float* Wo = (const float*)d_in[7];
    const float* bo = (const float*)d_in[8];
    float* out = (float*)d_out;

    cudaFuncSetAttribute(qkv_kernel,     cudaFuncAttributeMaxDynamicSharedMemorySize, GEMM_SMEM);
    cudaFuncSetAttribute(outproj_kernel, cudaFuncAttributeMaxDynamicSharedMemorySize, GEMM_SMEM);
    cudaFuncSetAttribute(attn_kernel,    cudaFuncAttributeMaxDynamicSharedMemorySize, ATT_SMEM);

    __nv_bfloat16 *xhi, *xlo, *wqh, *wql, *wkh, *wkl, *wvh, *wvl, *woh, *wol;
    cudaGetSymbolAddress((void**)&xhi, g_Xhi); cudaGetSymbolAddress((void**)&xlo, g_Xlo);
    cudaGetSymbolAddress((void**)&wqh, g_Wqh); cudaGetSymbolAddress((void**)&wql, g_Wql);
    cudaGetSymbolAddress((void**)&wkh, g_Wkh); cudaGetSymbolAddress((void**)&wkl, g_Wkl);
    cudaGetSymbolAddress((void**)&wvh, g_Wvh); cudaGetSymbolAddress((void**)&wvl, g_Wvl);
    cudaGetSymbolAddress((void**)&woh, g_Woh); cudaGetSymbolAddress((void**)&wol, g_Wol);

    split_kernel<<<MTOK*EMB/8/256, 256>>>(x,  xhi, xlo, MTOK*EMB/8);
    split_kernel<<<EMB*EMB/8/256,  256>>>(Wq, wqh, wql, EMB*EMB/8);
    split_kernel<<<EMB*EMB/8/256,  256>>>(Wk, wkh, wkl, EMB*EMB/8);
    split_kernel<<<EMB*EMB/8/256,  256>>>(Wv, wvh, wvl, EMB*EMB/8);
    split_kernel<<<EMB*EMB/8/256,  256>>>(Wo, woh, wol, EMB*EMB/8);

    dim3 gqkv(EMB/128, MTOK/128, 3);
    qkv_kernel<<<gqkv, 256, GEMM_SMEM>>>(bq, bk, bv);

    dim3 gattn(SEQ/128, BHN);
    attn_kernel<<<gattn, 256, ATT_SMEM>>>();

    dim3 gout(EMB/128, MTOK/128);
    outproj_kernel<<<gout, 256, GEMM_SMEM>>>(bo, out);
}